// round 5
// baseline (speedup 1.0000x reference)
#include <cuda_runtime.h>
#include <math.h>
#include <stdint.h>

#define HID 512
#define TI_A 32
#define TI_B 16

typedef unsigned long long ull;

__device__ __forceinline__ ull fma2(ull a, ull b, ull c) {
    ull d;
    asm("fma.rn.f32x2 %0, %1, %2, %3;" : "=l"(d) : "l"(a), "l"(b), "l"(c));
    return d;
}
__device__ __forceinline__ float2 unpack2(ull a) {
    float lo, hi;
    asm("mov.b64 {%0, %1}, %2;" : "=f"(lo), "=f"(hi) : "l"(a));
    return make_float2(lo, hi);
}

// Fallback scratch for attn if d_out doesn't include the attn tensor.
__device__ float g_attn_scratch[64 * 128 * 128];

// ---------------------------------------------------------------------------
// Kernel A: scores = Q K^T / sqrt(H), row softmax, write attn[b][i][j].
// Block: (batch b, 32-row i tile). 256 threads = (ty 0..7) x (tx 0..31).
// Thread micro-tile: 4 i x 4 j, j = {2tx, 2tx+1, 2tx+64, 2tx+65}.
// h processed in 16 chunks of 32 floats with DOUBLE-BUFFERED smem tiles:
// chunk c+1 global loads overlap chunk c compute.
// ---------------------------------------------------------------------------
__global__ __launch_bounds__(256) void qk_softmax_kernel(
    const float* __restrict__ q, const float* __restrict__ k,
    float* __restrict__ attn, int S)
{
    __shared__ ull Qs2[2][16][34];    // [buf][h2][i]
    __shared__ ull Ks2[2][16][130];   // [buf][h2][j]

    const int b   = blockIdx.x;
    const int i0  = blockIdx.y * TI_A;
    const int tid = threadIdx.x;
    const int tx  = tid & 31;
    const int ty  = tid >> 5;
    const int iy4 = ty * 4;
    const int h2l  = tx & 15;               // h-pair lane for loads (0..15)
    const int rsel = ty * 2 + (tx >> 4);    // row selector for loads (0..15)

    const float* qb = q + (size_t)b * S * HID;
    const float* kb = k + (size_t)b * S * HID;

    ull acc2[4][4];
#pragma unroll
    for (int a = 0; a < 4; ++a)
#pragma unroll
        for (int c = 0; c < 4; ++c) acc2[a][c] = 0ull;

    // chunk loader: 32 h-floats = 16 h-pairs starting at h0 = 32*c
    auto load_chunk = [&](int c, int buf) {
        int h0 = c * 32;
        // Q: 32 rows x 16 pairs
#pragma unroll
        for (int r = 0; r < 2; ++r) {
            int il = rsel + 16 * r;
            int i  = i0 + il;
            float2 val = (i < S) ? *(const float2*)(qb + (size_t)i * HID + h0 + h2l * 2)
                                 : make_float2(0.f, 0.f);
            *(float2*)&Qs2[buf][h2l][il] = val;
        }
        // K: 128 rows x 16 pairs
#pragma unroll
        for (int r = 0; r < 8; ++r) {
            int j = rsel + 16 * r;
            float2 val = (j < S) ? *(const float2*)(kb + (size_t)j * HID + h0 + h2l * 2)
                                 : make_float2(0.f, 0.f);
            *(float2*)&Ks2[buf][h2l][j] = val;
        }
    };

    load_chunk(0, 0);
    __syncthreads();

#pragma unroll 1
    for (int c = 0; c < 16; ++c) {
        int cur = c & 1;
        if (c + 1 < 16) load_chunk(c + 1, cur ^ 1);   // overlap with compute

#pragma unroll
        for (int h2 = 0; h2 < 16; ++h2) {
            ulonglong2 qa = *(const ulonglong2*)&Qs2[cur][h2][iy4];
            ulonglong2 qc = *(const ulonglong2*)&Qs2[cur][h2][iy4 + 2];
            ulonglong2 ka = *(const ulonglong2*)&Ks2[cur][h2][2 * tx];
            ulonglong2 kc = *(const ulonglong2*)&Ks2[cur][h2][2 * tx + 64];
            acc2[0][0] = fma2(qa.x, ka.x, acc2[0][0]);
            acc2[0][1] = fma2(qa.x, ka.y, acc2[0][1]);
            acc2[0][2] = fma2(qa.x, kc.x, acc2[0][2]);
            acc2[0][3] = fma2(qa.x, kc.y, acc2[0][3]);
            acc2[1][0] = fma2(qa.y, ka.x, acc2[1][0]);
            acc2[1][1] = fma2(qa.y, ka.y, acc2[1][1]);
            acc2[1][2] = fma2(qa.y, kc.x, acc2[1][2]);
            acc2[1][3] = fma2(qa.y, kc.y, acc2[1][3]);
            acc2[2][0] = fma2(qc.x, ka.x, acc2[2][0]);
            acc2[2][1] = fma2(qc.x, ka.y, acc2[2][1]);
            acc2[2][2] = fma2(qc.x, kc.x, acc2[2][2]);
            acc2[2][3] = fma2(qc.x, kc.y, acc2[2][3]);
            acc2[3][0] = fma2(qc.y, ka.x, acc2[3][0]);
            acc2[3][1] = fma2(qc.y, ka.y, acc2[3][1]);
            acc2[3][2] = fma2(qc.y, kc.x, acc2[3][2]);
            acc2[3][3] = fma2(qc.y, kc.y, acc2[3][3]);
        }
        __syncthreads();
    }

    const float inv_t = 0.04419417382415922f;  // 1/sqrt(512)

    const int c0 = 2 * tx;
    const int c2 = 2 * tx + 64;
    const bool v0 = (c0    ) < S;
    const bool v1 = (c0 + 1) < S;
    const bool v2 = (c2    ) < S;
    const bool v3 = (c2 + 1) < S;

#pragma unroll
    for (int si = 0; si < 4; ++si) {
        int i = i0 + iy4 + si;
        float2 a0 = unpack2(acc2[si][0]);
        float2 a1 = unpack2(acc2[si][1]);
        float2 a2 = unpack2(acc2[si][2]);
        float2 a3 = unpack2(acc2[si][3]);
        float s0 = v0 ? (a0.x + a0.y) * inv_t : -INFINITY;
        float s1 = v1 ? (a1.x + a1.y) * inv_t : -INFINITY;
        float s2 = v2 ? (a2.x + a2.y) * inv_t : -INFINITY;
        float s3 = v3 ? (a3.x + a3.y) * inv_t : -INFINITY;

        float m = fmaxf(fmaxf(s0, s1), fmaxf(s2, s3));
#pragma unroll
        for (int o = 16; o > 0; o >>= 1)
            m = fmaxf(m, __shfl_xor_sync(0xffffffffu, m, o));

        float e0 = __expf(s0 - m);
        float e1 = __expf(s1 - m);
        float e2 = __expf(s2 - m);
        float e3 = __expf(s3 - m);

        float sum = e0 + e1 + e2 + e3;
#pragma unroll
        for (int o = 16; o > 0; o >>= 1)
            sum += __shfl_xor_sync(0xffffffffu, sum, o);

        float rinv = 1.0f / sum;
        if (i < S) {
            float* row = attn + ((size_t)b * S + i) * S;
            if (v0) row[c0]     = e0 * rinv;
            if (v1) row[c0 + 1] = e1 * rinv;
            if (v2) row[c2]     = e2 * rinv;
            if (v3) row[c2 + 1] = e3 * rinv;
        }
    }
}

// ---------------------------------------------------------------------------
// Kernel B: F = attn @ V, then region-weight combine:
//   i <  S-1: out = w2*F + (w1-w2)*C + (w0-w1)*a_ii*v_i + (w3-w2)*a_iq*v_q
//   i == S-1: out = w4*F + (w5-w4)*a_qq*v_q
// Block: (batch b, 16-row i tile). 256 threads; thread t owns h = {2t, 2t+1}
// for ALL 16 rows. attn tile transposed in smem AsT[j][16] (plain float):
// per j: 4 broadcast LDS.128 + 1 coalesced LDG.64 feed 32 FFMA.
// ---------------------------------------------------------------------------
__global__ __launch_bounds__(256, 3) void out_kernel(
    const float* __restrict__ attn, const float* __restrict__ v,
    const float* __restrict__ aw, const int* __restrict__ Kp,
    float* __restrict__ out, int S)
{
    __shared__ float AsT[102][16];   // [j][ii]

    const int b  = blockIdx.x;
    const int i0 = blockIdx.y * TI_B;
    const int t  = threadIdx.x;      // 0..255
    const int h  = 2 * t;

    const float* vb = v + (size_t)b * S * HID;

    // Stage attn tile transposed (global reads coalesced over j)
    for (int idx = t; idx < TI_B * 102; idx += 256) {
        int ii = idx / 102;
        int jj = idx - ii * 102;
        int i  = i0 + ii;
        float a = (i < S && jj < S) ? attn[((size_t)b * S + i) * S + jj] : 0.f;
        AsT[jj][ii] = a;
    }
    __syncthreads();

    float2 F[16];
#pragma unroll
    for (int ii = 0; ii < 16; ++ii) F[ii] = make_float2(0.f, 0.f);

    // F accumulation: per j, 4 broadcast LDS.128 + 1 LDG.64 + 32 FFMA
    float2 vn = *(const float2*)(vb + h);
#pragma unroll 2
    for (int j = 0; j < S; ++j) {
        float2 vc = vn;
        if (j + 1 < S) vn = *(const float2*)(vb + (size_t)(j + 1) * HID + h);
        float4 a0 = *(const float4*)&AsT[j][0];
        float4 a1 = *(const float4*)&AsT[j][4];
        float4 a2 = *(const float4*)&AsT[j][8];
        float4 a3 = *(const float4*)&AsT[j][12];
        F[0].x  += a0.x * vc.x;  F[0].y  += a0.x * vc.y;
        F[1].x  += a0.y * vc.x;  F[1].y  += a0.y * vc.y;
        F[2].x  += a0.z * vc.x;  F[2].y  += a0.z * vc.y;
        F[3].x  += a0.w * vc.x;  F[3].y  += a0.w * vc.y;
        F[4].x  += a1.x * vc.x;  F[4].y  += a1.x * vc.y;
        F[5].x  += a1.y * vc.x;  F[5].y  += a1.y * vc.y;
        F[6].x  += a1.z * vc.x;  F[6].y  += a1.z * vc.y;
        F[7].x  += a1.w * vc.x;  F[7].y  += a1.w * vc.y;
        F[8].x  += a2.x * vc.x;  F[8].y  += a2.x * vc.y;
        F[9].x  += a2.y * vc.x;  F[9].y  += a2.y * vc.y;
        F[10].x += a2.z * vc.x;  F[10].y += a2.z * vc.y;
        F[11].x += a2.w * vc.x;  F[11].y += a2.w * vc.y;
        F[12].x += a3.x * vc.x;  F[12].y += a3.x * vc.y;
        F[13].x += a3.y * vc.x;  F[13].y += a3.y * vc.y;
        F[14].x += a3.z * vc.x;  F[14].y += a3.z * vc.y;
        F[15].x += a3.w * vc.x;  F[15].y += a3.w * vc.y;
    }

    // Weight vectors at this 2-wide h slice
    const float2 w0 = *(const float2*)(aw + 0 * HID + h);
    const float2 w1 = *(const float2*)(aw + 1 * HID + h);
    const float2 w2 = *(const float2*)(aw + 2 * HID + h);
    const float2 w3 = *(const float2*)(aw + 3 * HID + h);
    const float2 w4 = *(const float2*)(aw + 4 * HID + h);
    const float2 w5 = *(const float2*)(aw + 5 * HID + h);

    const float2 d12 = make_float2(w1.x - w2.x, w1.y - w2.y);
    const float2 d01 = make_float2(w0.x - w1.x, w0.y - w1.y);
    const float2 d32 = make_float2(w3.x - w2.x, w3.y - w2.y);
    const float2 d54 = make_float2(w5.x - w4.x, w5.y - w4.y);

    int Kv = 10;
    if (Kp != nullptr) {
        int kk = __ldg(Kp);
        if (kk > 0 && kk <= S) Kv = kk;
    }
    const int NKq = S - 1;
    const float2 vq = *(const float2*)(vb + (size_t)NKq * HID + h);

#pragma unroll 1
    for (int ii = 0; ii < 16; ++ii) {
        int i = i0 + ii;
        if (i >= S) break;
        float2 o;

        if (i == NKq) {
            float aqq = AsT[NKq][ii];
            o.x = w4.x * F[ii].x + d54.x * aqq * vq.x;
            o.y = w4.y * F[ii].y + d54.y * aqq * vq.y;
        } else {
            int cb   = (i / Kv) * Kv;
            int cend = cb + Kv;
            if (cend > NKq) cend = NKq;  // class region never includes the query col
            float2 C = make_float2(0.f, 0.f);
            for (int jj = cb; jj < cend; ++jj) {
                float a = AsT[jj][ii];
                float2 vv = *(const float2*)(vb + (size_t)jj * HID + h);
                C.x += a * vv.x; C.y += a * vv.y;
            }
            float aii = AsT[i][ii];      // attn[i][i]
            float aiq = AsT[NKq][ii];
            float2 vi = *(const float2*)(vb + (size_t)i * HID + h);

            o.x = w2.x * F[ii].x + d12.x * C.x + d01.x * aii * vi.x + d32.x * aiq * vq.x;
            o.y = w2.y * F[ii].y + d12.y * C.y + d01.y * aii * vi.y + d32.y * aiq * vq.y;
        }
        *(float2*)(out + ((size_t)b * S + i) * HID + h) = o;
    }
}

// ---------------------------------------------------------------------------
extern "C" void kernel_launch(void* const* d_in, const int* in_sizes, int n_in,
                              void* d_out, int out_size)
{
    const float* q  = (const float*)d_in[0];
    const float* k  = (const float*)d_in[1];
    const float* v  = (const float*)d_in[2];
    const float* aw = (const float*)d_in[3];
    const int*   Kp = (n_in >= 6) ? (const int*)d_in[5] : nullptr;

    long rows = (long)in_sizes[0] / HID;   // B * S
    int B = 64;
    int S = (int)(rows / B);
    if (S <= 0 || (long)B * S != rows) { B = 1; S = (int)rows; }

    float* out = (float*)d_out;
    long need_with_attn = (long)B * S * HID + (long)B * S * S;
    float* attn;
    if ((long)out_size >= need_with_attn) {
        attn = out + (long)B * S * HID;
    } else {
        void* p = nullptr;
        cudaGetSymbolAddress(&p, g_attn_scratch);
        attn = (float*)p;
    }

    dim3 gA(B, (S + TI_A - 1) / TI_A);
    qk_softmax_kernel<<<gA, 256>>>(q, k, attn, S);

    dim3 gB(B, (S + TI_B - 1) / TI_B);
    out_kernel<<<gB, 256>>>(attn, v, aw, Kp, out, S);
}

// round 6
// speedup vs baseline: 1.0259x; 1.0259x over previous
#include <cuda_runtime.h>
#include <math.h>
#include <stdint.h>

#define HID 512
#define TI_A 32
#define TI_B 16

typedef unsigned long long ull;

__device__ __forceinline__ ull fma2(ull a, ull b, ull c) {
    ull d;
    asm("fma.rn.f32x2 %0, %1, %2, %3;" : "=l"(d) : "l"(a), "l"(b), "l"(c));
    return d;
}
__device__ __forceinline__ float2 unpack2(ull a) {
    float lo, hi;
    asm("mov.b64 {%0, %1}, %2;" : "=f"(lo), "=f"(hi) : "l"(a));
    return make_float2(lo, hi);
}

// Fallback scratch for attn if d_out doesn't include the attn tensor.
__device__ float g_attn_scratch[64 * 128 * 128];

// ---------------------------------------------------------------------------
// Kernel A: scores = Q K^T / sqrt(H), row softmax, write attn[b][i][j].
// Block: (batch b, 32-row i tile). 256 threads = (ty 0..7) x (tx 0..31).
// Thread micro-tile: 4 i x 4 j, j = {2tx, 2tx+1, 2tx+64, 2tx+65}.
// h processed in 16 chunks of 32 floats with DOUBLE-BUFFERED smem tiles.
// ---------------------------------------------------------------------------
__global__ __launch_bounds__(256) void qk_softmax_kernel(
    const float* __restrict__ q, const float* __restrict__ k,
    float* __restrict__ attn, int S)
{
    __shared__ ull Qs2[2][16][34];    // [buf][h2][i]
    __shared__ ull Ks2[2][16][130];   // [buf][h2][j]

    const int b   = blockIdx.x;
    const int i0  = blockIdx.y * TI_A;
    const int tid = threadIdx.x;
    const int tx  = tid & 31;
    const int ty  = tid >> 5;
    const int iy4 = ty * 4;
    const int h2l  = tx & 15;               // h-pair lane for loads (0..15)
    const int rsel = ty * 2 + (tx >> 4);    // row selector for loads (0..15)

    const float* qb = q + (size_t)b * S * HID;
    const float* kb = k + (size_t)b * S * HID;

    ull acc2[4][4];
#pragma unroll
    for (int a = 0; a < 4; ++a)
#pragma unroll
        for (int c = 0; c < 4; ++c) acc2[a][c] = 0ull;

    auto load_chunk = [&](int c, int buf) {
        int h0 = c * 32;
#pragma unroll
        for (int r = 0; r < 2; ++r) {
            int il = rsel + 16 * r;
            int i  = i0 + il;
            float2 val = (i < S) ? *(const float2*)(qb + (size_t)i * HID + h0 + h2l * 2)
                                 : make_float2(0.f, 0.f);
            *(float2*)&Qs2[buf][h2l][il] = val;
        }
#pragma unroll
        for (int r = 0; r < 8; ++r) {
            int j = rsel + 16 * r;
            float2 val = (j < S) ? *(const float2*)(kb + (size_t)j * HID + h0 + h2l * 2)
                                 : make_float2(0.f, 0.f);
            *(float2*)&Ks2[buf][h2l][j] = val;
        }
    };

    load_chunk(0, 0);
    __syncthreads();

#pragma unroll 1
    for (int c = 0; c < 16; ++c) {
        int cur = c & 1;
        if (c + 1 < 16) load_chunk(c + 1, cur ^ 1);   // overlap with compute

#pragma unroll
        for (int h2 = 0; h2 < 16; ++h2) {
            ulonglong2 qa = *(const ulonglong2*)&Qs2[cur][h2][iy4];
            ulonglong2 qc = *(const ulonglong2*)&Qs2[cur][h2][iy4 + 2];
            ulonglong2 ka = *(const ulonglong2*)&Ks2[cur][h2][2 * tx];
            ulonglong2 kc = *(const ulonglong2*)&Ks2[cur][h2][2 * tx + 64];
            acc2[0][0] = fma2(qa.x, ka.x, acc2[0][0]);
            acc2[0][1] = fma2(qa.x, ka.y, acc2[0][1]);
            acc2[0][2] = fma2(qa.x, kc.x, acc2[0][2]);
            acc2[0][3] = fma2(qa.x, kc.y, acc2[0][3]);
            acc2[1][0] = fma2(qa.y, ka.x, acc2[1][0]);
            acc2[1][1] = fma2(qa.y, ka.y, acc2[1][1]);
            acc2[1][2] = fma2(qa.y, kc.x, acc2[1][2]);
            acc2[1][3] = fma2(qa.y, kc.y, acc2[1][3]);
            acc2[2][0] = fma2(qc.x, ka.x, acc2[2][0]);
            acc2[2][1] = fma2(qc.x, ka.y, acc2[2][1]);
            acc2[2][2] = fma2(qc.x, kc.x, acc2[2][2]);
            acc2[2][3] = fma2(qc.x, kc.y, acc2[2][3]);
            acc2[3][0] = fma2(qc.y, ka.x, acc2[3][0]);
            acc2[3][1] = fma2(qc.y, ka.y, acc2[3][1]);
            acc2[3][2] = fma2(qc.y, kc.x, acc2[3][2]);
            acc2[3][3] = fma2(qc.y, kc.y, acc2[3][3]);
        }
        __syncthreads();
    }

    const float inv_t = 0.04419417382415922f;  // 1/sqrt(512)

    const int c0 = 2 * tx;
    const int c2 = 2 * tx + 64;
    const bool v0 = (c0    ) < S;
    const bool v1 = (c0 + 1) < S;
    const bool v2 = (c2    ) < S;
    const bool v3 = (c2 + 1) < S;

#pragma unroll
    for (int si = 0; si < 4; ++si) {
        int i = i0 + iy4 + si;
        float2 a0 = unpack2(acc2[si][0]);
        float2 a1 = unpack2(acc2[si][1]);
        float2 a2 = unpack2(acc2[si][2]);
        float2 a3 = unpack2(acc2[si][3]);
        float s0 = v0 ? (a0.x + a0.y) * inv_t : -INFINITY;
        float s1 = v1 ? (a1.x + a1.y) * inv_t : -INFINITY;
        float s2 = v2 ? (a2.x + a2.y) * inv_t : -INFINITY;
        float s3 = v3 ? (a3.x + a3.y) * inv_t : -INFINITY;

        float m = fmaxf(fmaxf(s0, s1), fmaxf(s2, s3));
#pragma unroll
        for (int o = 16; o > 0; o >>= 1)
            m = fmaxf(m, __shfl_xor_sync(0xffffffffu, m, o));

        float e0 = __expf(s0 - m);
        float e1 = __expf(s1 - m);
        float e2 = __expf(s2 - m);
        float e3 = __expf(s3 - m);

        float sum = e0 + e1 + e2 + e3;
#pragma unroll
        for (int o = 16; o > 0; o >>= 1)
            sum += __shfl_xor_sync(0xffffffffu, sum, o);

        float rinv = 1.0f / sum;
        if (i < S) {
            float* row = attn + ((size_t)b * S + i) * S;
            if (v0) row[c0]     = e0 * rinv;
            if (v1) row[c0 + 1] = e1 * rinv;
            if (v2) row[c2]     = e2 * rinv;
            if (v3) row[c2 + 1] = e3 * rinv;
        }
    }
}

// ---------------------------------------------------------------------------
// Kernel B: F = attn @ V, then region-weight combine:
//   i <  S-1: out = w2*F + (w1-w2)*C + (w0-w1)*a_ii*v_i + (w3-w2)*a_iq*v_q
//   i == S-1: out = w4*F + (w5-w4)*a_qq*v_q
// Block: (batch b, 16-row i tile). 256 threads; thread t owns h = {2t, 2t+1}
// for ALL 16 rows. attn tile transposed AsT[j][16]; per j: 4 broadcast
// LDS.128 + 32 FFMA. V prefetched 4 DEEP in registers (j unrolled x4) so
// each SMSP has ~24 outstanding LDGs -> L2 latency fully covered.
// ---------------------------------------------------------------------------
__global__ __launch_bounds__(256, 3) void out_kernel(
    const float* __restrict__ attn, const float* __restrict__ v,
    const float* __restrict__ aw, const int* __restrict__ Kp,
    float* __restrict__ out, int S)
{
    __shared__ float AsT[102][16];   // [j][ii]

    const int b  = blockIdx.x;
    const int i0 = blockIdx.y * TI_B;
    const int t  = threadIdx.x;      // 0..255
    const int h  = 2 * t;

    const float* vb = v + (size_t)b * S * HID;

    // Stage attn tile transposed (global reads coalesced over j)
    for (int idx = t; idx < TI_B * 102; idx += 256) {
        int ii = idx / 102;
        int jj = idx - ii * 102;
        int i  = i0 + ii;
        float a = (i < S && jj < S) ? attn[((size_t)b * S + i) * S + jj] : 0.f;
        AsT[jj][ii] = a;
    }
    __syncthreads();

    float2 F[16];
#pragma unroll
    for (int ii = 0; ii < 16; ++ii) F[ii] = make_float2(0.f, 0.f);

    const float2 fz = make_float2(0.f, 0.f);

    // per-j FMA body: 4 broadcast LDS.128 + 32 FFMA
    auto proc = [&](int j, float2 vc) {
        float4 a0 = *(const float4*)&AsT[j][0];
        float4 a1 = *(const float4*)&AsT[j][4];
        float4 a2 = *(const float4*)&AsT[j][8];
        float4 a3 = *(const float4*)&AsT[j][12];
        F[0].x  += a0.x * vc.x;  F[0].y  += a0.x * vc.y;
        F[1].x  += a0.y * vc.x;  F[1].y  += a0.y * vc.y;
        F[2].x  += a0.z * vc.x;  F[2].y  += a0.z * vc.y;
        F[3].x  += a0.w * vc.x;  F[3].y  += a0.w * vc.y;
        F[4].x  += a1.x * vc.x;  F[4].y  += a1.x * vc.y;
        F[5].x  += a1.y * vc.x;  F[5].y  += a1.y * vc.y;
        F[6].x  += a1.z * vc.x;  F[6].y  += a1.z * vc.y;
        F[7].x  += a1.w * vc.x;  F[7].y  += a1.w * vc.y;
        F[8].x  += a2.x * vc.x;  F[8].y  += a2.x * vc.y;
        F[9].x  += a2.y * vc.x;  F[9].y  += a2.y * vc.y;
        F[10].x += a2.z * vc.x;  F[10].y += a2.z * vc.y;
        F[11].x += a2.w * vc.x;  F[11].y += a2.w * vc.y;
        F[12].x += a3.x * vc.x;  F[12].y += a3.x * vc.y;
        F[13].x += a3.y * vc.x;  F[13].y += a3.y * vc.y;
        F[14].x += a3.z * vc.x;  F[14].y += a3.z * vc.y;
        F[15].x += a3.w * vc.x;  F[15].y += a3.w * vc.y;
    };

    // 4-deep prefetch ring
    float2 p0 = (0 < S) ? *(const float2*)(vb + 0 * (size_t)HID + h) : fz;
    float2 p1 = (1 < S) ? *(const float2*)(vb + 1 * (size_t)HID + h) : fz;
    float2 p2 = (2 < S) ? *(const float2*)(vb + 2 * (size_t)HID + h) : fz;
    float2 p3 = (3 < S) ? *(const float2*)(vb + 3 * (size_t)HID + h) : fz;

    int j = 0;
#pragma unroll 1
    for (; j + 3 < S; j += 4) {
        // issue next 4 loads first (max distance to use)
        float2 n0 = (j + 4 < S) ? *(const float2*)(vb + (size_t)(j + 4) * HID + h) : fz;
        float2 n1 = (j + 5 < S) ? *(const float2*)(vb + (size_t)(j + 5) * HID + h) : fz;
        float2 n2 = (j + 6 < S) ? *(const float2*)(vb + (size_t)(j + 6) * HID + h) : fz;
        float2 n3 = (j + 7 < S) ? *(const float2*)(vb + (size_t)(j + 7) * HID + h) : fz;
        proc(j + 0, p0);
        proc(j + 1, p1);
        proc(j + 2, p2);
        proc(j + 3, p3);
        p0 = n0; p1 = n1; p2 = n2; p3 = n3;
    }
    // tail (<= 3 iterations), ring already holds V[j..]
    if (j < S)     proc(j,     p0);
    if (j + 1 < S) proc(j + 1, p1);
    if (j + 2 < S) proc(j + 2, p2);

    // Weight vectors at this 2-wide h slice
    const float2 w0 = *(const float2*)(aw + 0 * HID + h);
    const float2 w1 = *(const float2*)(aw + 1 * HID + h);
    const float2 w2 = *(const float2*)(aw + 2 * HID + h);
    const float2 w3 = *(const float2*)(aw + 3 * HID + h);
    const float2 w4 = *(const float2*)(aw + 4 * HID + h);
    const float2 w5 = *(const float2*)(aw + 5 * HID + h);

    const float2 d12 = make_float2(w1.x - w2.x, w1.y - w2.y);
    const float2 d01 = make_float2(w0.x - w1.x, w0.y - w1.y);
    const float2 d32 = make_float2(w3.x - w2.x, w3.y - w2.y);
    const float2 d54 = make_float2(w5.x - w4.x, w5.y - w4.y);

    int Kv = 10;
    if (Kp != nullptr) {
        int kk = __ldg(Kp);
        if (kk > 0 && kk <= S) Kv = kk;
    }
    const int NKq = S - 1;
    const float2 vq = *(const float2*)(vb + (size_t)NKq * HID + h);

#pragma unroll 1
    for (int ii = 0; ii < 16; ++ii) {
        int i = i0 + ii;
        if (i >= S) break;
        float2 o;

        if (i == NKq) {
            float aqq = AsT[NKq][ii];
            o.x = w4.x * F[ii].x + d54.x * aqq * vq.x;
            o.y = w4.y * F[ii].y + d54.y * aqq * vq.y;
        } else {
            int cb   = (i / Kv) * Kv;
            int cend = cb + Kv;
            if (cend > NKq) cend = NKq;  // class region never includes the query col
            float2 C = make_float2(0.f, 0.f);
            for (int jj = cb; jj < cend; ++jj) {
                float a = AsT[jj][ii];
                float2 vv = *(const float2*)(vb + (size_t)jj * HID + h);
                C.x += a * vv.x; C.y += a * vv.y;
            }
            float aii = AsT[i][ii];      // attn[i][i]
            float aiq = AsT[NKq][ii];
            float2 vi = *(const float2*)(vb + (size_t)i * HID + h);

            o.x = w2.x * F[ii].x + d12.x * C.x + d01.x * aii * vi.x + d32.x * aiq * vq.x;
            o.y = w2.y * F[ii].y + d12.y * C.y + d01.y * aii * vi.y + d32.y * aiq * vq.y;
        }
        *(float2*)(out + ((size_t)b * S + i) * HID + h) = o;
    }
}

// ---------------------------------------------------------------------------
extern "C" void kernel_launch(void* const* d_in, const int* in_sizes, int n_in,
                              void* d_out, int out_size)
{
    const float* q  = (const float*)d_in[0];
    const float* k  = (const float*)d_in[1];
    const float* v  = (const float*)d_in[2];
    const float* aw = (const float*)d_in[3];
    const int*   Kp = (n_in >= 6) ? (const int*)d_in[5] : nullptr;

    long rows = (long)in_sizes[0] / HID;   // B * S
    int B = 64;
    int S = (int)(rows / B);
    if (S <= 0 || (long)B * S != rows) { B = 1; S = (int)rows; }

    float* out = (float*)d_out;
    long need_with_attn = (long)B * S * HID + (long)B * S * S;
    float* attn;
    if ((long)out_size >= need_with_attn) {
        attn = out + (long)B * S * HID;
    } else {
        void* p = nullptr;
        cudaGetSymbolAddress(&p, g_attn_scratch);
        attn = (float*)p;
    }

    dim3 gA(B, (S + TI_A - 1) / TI_A);
    qk_softmax_kernel<<<gA, 256>>>(q, k, attn, S);

    dim3 gB(B, (S + TI_B - 1) / TI_B);
    out_kernel<<<gB, 256>>>(attn, v, aw, Kp, out, S);
}

// round 7
// speedup vs baseline: 1.0442x; 1.0178x over previous
#include <cuda_runtime.h>
#include <math.h>
#include <stdint.h>

#define HID 512
#define TI_A 32
#define TI_B 16

typedef unsigned long long ull;

__device__ __forceinline__ ull fma2(ull a, ull b, ull c) {
    ull d;
    asm("fma.rn.f32x2 %0, %1, %2, %3;" : "=l"(d) : "l"(a), "l"(b), "l"(c));
    return d;
}
__device__ __forceinline__ ull pack2(float lo, float hi) {
    ull d;
    asm("mov.b64 %0, {%1, %2};" : "=l"(d) : "f"(lo), "f"(hi));
    return d;
}
__device__ __forceinline__ float2 unpack2(ull a) {
    float lo, hi;
    asm("mov.b64 {%0, %1}, %2;" : "=f"(lo), "=f"(hi) : "l"(a));
    return make_float2(lo, hi);
}

// Fallback scratch for attn if d_out doesn't include the attn tensor.
__device__ float g_attn_scratch[64 * 128 * 128];

// ---------------------------------------------------------------------------
// Kernel A: scores = Q K^T / sqrt(H), row softmax, write attn[b][i][j].
// Block: (batch b, 32-row i tile). 256 threads = (ty 0..7) x (tx 0..31).
// Thread micro-tile: 4 i x 4 j, j = {2tx, 2tx+1, 2tx+64, 2tx+65}.
// h processed in 16 chunks of 32 floats with DOUBLE-BUFFERED smem tiles.
// ---------------------------------------------------------------------------
__global__ __launch_bounds__(256) void qk_softmax_kernel(
    const float* __restrict__ q, const float* __restrict__ k,
    float* __restrict__ attn, int S)
{
    __shared__ ull Qs2[2][16][34];    // [buf][h2][i]
    __shared__ ull Ks2[2][16][130];   // [buf][h2][j]

    const int b   = blockIdx.x;
    const int i0  = blockIdx.y * TI_A;
    const int tid = threadIdx.x;
    const int tx  = tid & 31;
    const int ty  = tid >> 5;
    const int iy4 = ty * 4;
    const int h2l  = tx & 15;               // h-pair lane for loads (0..15)
    const int rsel = ty * 2 + (tx >> 4);    // row selector for loads (0..15)

    const float* qb = q + (size_t)b * S * HID;
    const float* kb = k + (size_t)b * S * HID;

    ull acc2[4][4];
#pragma unroll
    for (int a = 0; a < 4; ++a)
#pragma unroll
        for (int c = 0; c < 4; ++c) acc2[a][c] = 0ull;

    auto load_chunk = [&](int c, int buf) {
        int h0 = c * 32;
#pragma unroll
        for (int r = 0; r < 2; ++r) {
            int il = rsel + 16 * r;
            int i  = i0 + il;
            float2 val = (i < S) ? *(const float2*)(qb + (size_t)i * HID + h0 + h2l * 2)
                                 : make_float2(0.f, 0.f);
            *(float2*)&Qs2[buf][h2l][il] = val;
        }
#pragma unroll
        for (int r = 0; r < 8; ++r) {
            int j = rsel + 16 * r;
            float2 val = (j < S) ? *(const float2*)(kb + (size_t)j * HID + h0 + h2l * 2)
                                 : make_float2(0.f, 0.f);
            *(float2*)&Ks2[buf][h2l][j] = val;
        }
    };

    load_chunk(0, 0);
    __syncthreads();

#pragma unroll 1
    for (int c = 0; c < 16; ++c) {
        int cur = c & 1;
        if (c + 1 < 16) load_chunk(c + 1, cur ^ 1);   // overlap with compute

#pragma unroll
        for (int h2 = 0; h2 < 16; ++h2) {
            ulonglong2 qa = *(const ulonglong2*)&Qs2[cur][h2][iy4];
            ulonglong2 qc = *(const ulonglong2*)&Qs2[cur][h2][iy4 + 2];
            ulonglong2 ka = *(const ulonglong2*)&Ks2[cur][h2][2 * tx];
            ulonglong2 kc = *(const ulonglong2*)&Ks2[cur][h2][2 * tx + 64];
            acc2[0][0] = fma2(qa.x, ka.x, acc2[0][0]);
            acc2[0][1] = fma2(qa.x, ka.y, acc2[0][1]);
            acc2[0][2] = fma2(qa.x, kc.x, acc2[0][2]);
            acc2[0][3] = fma2(qa.x, kc.y, acc2[0][3]);
            acc2[1][0] = fma2(qa.y, ka.x, acc2[1][0]);
            acc2[1][1] = fma2(qa.y, ka.y, acc2[1][1]);
            acc2[1][2] = fma2(qa.y, kc.x, acc2[1][2]);
            acc2[1][3] = fma2(qa.y, kc.y, acc2[1][3]);
            acc2[2][0] = fma2(qc.x, ka.x, acc2[2][0]);
            acc2[2][1] = fma2(qc.x, ka.y, acc2[2][1]);
            acc2[2][2] = fma2(qc.x, kc.x, acc2[2][2]);
            acc2[2][3] = fma2(qc.x, kc.y, acc2[2][3]);
            acc2[3][0] = fma2(qc.y, ka.x, acc2[3][0]);
            acc2[3][1] = fma2(qc.y, ka.y, acc2[3][1]);
            acc2[3][2] = fma2(qc.y, kc.x, acc2[3][2]);
            acc2[3][3] = fma2(qc.y, kc.y, acc2[3][3]);
        }
        __syncthreads();
    }

    const float inv_t = 0.04419417382415922f;  // 1/sqrt(512)

    const int c0 = 2 * tx;
    const int c2 = 2 * tx + 64;
    const bool v0 = (c0    ) < S;
    const bool v1 = (c0 + 1) < S;
    const bool v2 = (c2    ) < S;
    const bool v3 = (c2 + 1) < S;

#pragma unroll
    for (int si = 0; si < 4; ++si) {
        int i = i0 + iy4 + si;
        float2 a0 = unpack2(acc2[si][0]);
        float2 a1 = unpack2(acc2[si][1]);
        float2 a2 = unpack2(acc2[si][2]);
        float2 a3 = unpack2(acc2[si][3]);
        float s0 = v0 ? (a0.x + a0.y) * inv_t : -INFINITY;
        float s1 = v1 ? (a1.x + a1.y) * inv_t : -INFINITY;
        float s2 = v2 ? (a2.x + a2.y) * inv_t : -INFINITY;
        float s3 = v3 ? (a3.x + a3.y) * inv_t : -INFINITY;

        float m = fmaxf(fmaxf(s0, s1), fmaxf(s2, s3));
#pragma unroll
        for (int o = 16; o > 0; o >>= 1)
            m = fmaxf(m, __shfl_xor_sync(0xffffffffu, m, o));

        float e0 = __expf(s0 - m);
        float e1 = __expf(s1 - m);
        float e2 = __expf(s2 - m);
        float e3 = __expf(s3 - m);

        float sum = e0 + e1 + e2 + e3;
#pragma unroll
        for (int o = 16; o > 0; o >>= 1)
            sum += __shfl_xor_sync(0xffffffffu, sum, o);

        float rinv = 1.0f / sum;
        if (i < S) {
            float* row = attn + ((size_t)b * S + i) * S;
            if (v0) row[c0]     = e0 * rinv;
            if (v1) row[c0 + 1] = e1 * rinv;
            if (v2) row[c2]     = e2 * rinv;
            if (v3) row[c2 + 1] = e3 * rinv;
        }
    }
}

// ---------------------------------------------------------------------------
// Kernel B: F = attn @ V, then region-weight combine:
//   i <  S-1: out = w2*F + (w1-w2)*C + (w0-w1)*a_ii*v_i + (w3-w2)*a_iq*v_q
//   i == S-1: out = w4*F + (w5-w4)*a_qq*v_q
// Block: (batch b, 16-row i tile). 256 threads; thread t owns h = {2t, 2t+1}
// for ALL 16 rows. attn transposed AsT[j][16]: 4 LDS.128 per j give 8
// row-pair ulls that feed fma.rn.f32x2 directly — F for rows (2r, 2r+1) at
// one h accumulate in the two halves of one ull. Per j per warp:
// 1 LDG.64 + 2 dup-MOV + 4 LDS.128 + 16 fma2 (was 64 FFMA).
// V prefetched 4 deep in registers.
// ---------------------------------------------------------------------------
__global__ __launch_bounds__(256, 3) void out_kernel(
    const float* __restrict__ attn, const float* __restrict__ v,
    const float* __restrict__ aw, const int* __restrict__ Kp,
    float* __restrict__ out, int S)
{
    __shared__ float AsT[102][16];   // [j][ii], 64B per j -> LDS.128 aligned

    const int b  = blockIdx.x;
    const int i0 = blockIdx.y * TI_B;
    const int t  = threadIdx.x;      // 0..255
    const int h  = 2 * t;

    const float* vb = v + (size_t)b * S * HID;

    // Stage attn tile transposed (global reads coalesced over j)
    for (int idx = t; idx < TI_B * 102; idx += 256) {
        int ii = idx / 102;
        int jj = idx - ii * 102;
        int i  = i0 + ii;
        float a = (i < S && jj < S) ? attn[((size_t)b * S + i) * S + jj] : 0.f;
        AsT[jj][ii] = a;
    }
    __syncthreads();

    // F0[r] = (F[2r][h],   F[2r+1][h])
    // F1[r] = (F[2r][h+1], F[2r+1][h+1])
    ull F0[8], F1[8];
#pragma unroll
    for (int r = 0; r < 8; ++r) { F0[r] = 0ull; F1[r] = 0ull; }

    const float2 fz = make_float2(0.f, 0.f);

    auto body = [&](int j, float2 vc) {
        ull vlo = pack2(vc.x, vc.x);   // dup V[j][h]
        ull vhi = pack2(vc.y, vc.y);   // dup V[j][h+1]
        ulonglong2 a01 = *(const ulonglong2*)&AsT[j][0];
        ulonglong2 a23 = *(const ulonglong2*)&AsT[j][4];
        ulonglong2 a45 = *(const ulonglong2*)&AsT[j][8];
        ulonglong2 a67 = *(const ulonglong2*)&AsT[j][12];
        F0[0] = fma2(vlo, a01.x, F0[0]);  F1[0] = fma2(vhi, a01.x, F1[0]);
        F0[1] = fma2(vlo, a01.y, F0[1]);  F1[1] = fma2(vhi, a01.y, F1[1]);
        F0[2] = fma2(vlo, a23.x, F0[2]);  F1[2] = fma2(vhi, a23.x, F1[2]);
        F0[3] = fma2(vlo, a23.y, F0[3]);  F1[3] = fma2(vhi, a23.y, F1[3]);
        F0[4] = fma2(vlo, a45.x, F0[4]);  F1[4] = fma2(vhi, a45.x, F1[4]);
        F0[5] = fma2(vlo, a45.y, F0[5]);  F1[5] = fma2(vhi, a45.y, F1[5]);
        F0[6] = fma2(vlo, a67.x, F0[6]);  F1[6] = fma2(vhi, a67.x, F1[6]);
        F0[7] = fma2(vlo, a67.y, F0[7]);  F1[7] = fma2(vhi, a67.y, F1[7]);
    };

    // 4-deep prefetch ring
    float2 p0 = (0 < S) ? *(const float2*)(vb + 0 * (size_t)HID + h) : fz;
    float2 p1 = (1 < S) ? *(const float2*)(vb + 1 * (size_t)HID + h) : fz;
    float2 p2 = (2 < S) ? *(const float2*)(vb + 2 * (size_t)HID + h) : fz;
    float2 p3 = (3 < S) ? *(const float2*)(vb + 3 * (size_t)HID + h) : fz;

    int j = 0;
#pragma unroll 1
    for (; j + 3 < S; j += 4) {
        float2 n0 = (j + 4 < S) ? *(const float2*)(vb + (size_t)(j + 4) * HID + h) : fz;
        float2 n1 = (j + 5 < S) ? *(const float2*)(vb + (size_t)(j + 5) * HID + h) : fz;
        float2 n2 = (j + 6 < S) ? *(const float2*)(vb + (size_t)(j + 6) * HID + h) : fz;
        float2 n3 = (j + 7 < S) ? *(const float2*)(vb + (size_t)(j + 7) * HID + h) : fz;
        body(j + 0, p0);
        body(j + 1, p1);
        body(j + 2, p2);
        body(j + 3, p3);
        p0 = n0; p1 = n1; p2 = n2; p3 = n3;
    }
    if (j < S)     body(j,     p0);
    if (j + 1 < S) body(j + 1, p1);
    if (j + 2 < S) body(j + 2, p2);

    // Unpack F into per-row (h, h+1) pairs
    float Fx[16], Fy[16];
#pragma unroll
    for (int r = 0; r < 8; ++r) {
        float2 u0 = unpack2(F0[r]);
        float2 u1 = unpack2(F1[r]);
        Fx[2 * r]     = u0.x;  Fx[2 * r + 1] = u0.y;
        Fy[2 * r]     = u1.x;  Fy[2 * r + 1] = u1.y;
    }

    // Weight vectors at this 2-wide h slice
    const float2 w0 = *(const float2*)(aw + 0 * HID + h);
    const float2 w1 = *(const float2*)(aw + 1 * HID + h);
    const float2 w2 = *(const float2*)(aw + 2 * HID + h);
    const float2 w3 = *(const float2*)(aw + 3 * HID + h);
    const float2 w4 = *(const float2*)(aw + 4 * HID + h);
    const float2 w5 = *(const float2*)(aw + 5 * HID + h);

    const float2 d12 = make_float2(w1.x - w2.x, w1.y - w2.y);
    const float2 d01 = make_float2(w0.x - w1.x, w0.y - w1.y);
    const float2 d32 = make_float2(w3.x - w2.x, w3.y - w2.y);
    const float2 d54 = make_float2(w5.x - w4.x, w5.y - w4.y);

    int Kv = 10;
    if (Kp != nullptr) {
        int kk = __ldg(Kp);
        if (kk > 0 && kk <= S) Kv = kk;
    }
    const int NKq = S - 1;
    const float2 vq = *(const float2*)(vb + (size_t)NKq * HID + h);

#pragma unroll 1
    for (int ii = 0; ii < 16; ++ii) {
        int i = i0 + ii;
        if (i >= S) break;
        float2 o;

        if (i == NKq) {
            float aqq = AsT[NKq][ii];
            o.x = w4.x * Fx[ii] + d54.x * aqq * vq.x;
            o.y = w4.y * Fy[ii] + d54.y * aqq * vq.y;
        } else {
            int cb   = (i / Kv) * Kv;
            int cend = cb + Kv;
            if (cend > NKq) cend = NKq;  // class region never includes the query col
            float2 C = make_float2(0.f, 0.f);
            for (int jj = cb; jj < cend; ++jj) {
                float a = AsT[jj][ii];
                float2 vv = *(const float2*)(vb + (size_t)jj * HID + h);
                C.x += a * vv.x; C.y += a * vv.y;
            }
            float aii = AsT[i][ii];      // attn[i][i]
            float aiq = AsT[NKq][ii];
            float2 vi = *(const float2*)(vb + (size_t)i * HID + h);

            o.x = w2.x * Fx[ii] + d12.x * C.x + d01.x * aii * vi.x + d32.x * aiq * vq.x;
            o.y = w2.y * Fy[ii] + d12.y * C.y + d01.y * aii * vi.y + d32.y * aiq * vq.y;
        }
        *(float2*)(out + ((size_t)b * S + i) * HID + h) = o;
    }
}

// ---------------------------------------------------------------------------
extern "C" void kernel_launch(void* const* d_in, const int* in_sizes, int n_in,
                              void* d_out, int out_size)
{
    const float* q  = (const float*)d_in[0];
    const float* k  = (const float*)d_in[1];
    const float* v  = (const float*)d_in[2];
    const float* aw = (const float*)d_in[3];
    const int*   Kp = (n_in >= 6) ? (const int*)d_in[5] : nullptr;

    long rows = (long)in_sizes[0] / HID;   // B * S
    int B = 64;
    int S = (int)(rows / B);
    if (S <= 0 || (long)B * S != rows) { B = 1; S = (int)rows; }

    float* out = (float*)d_out;
    long need_with_attn = (long)B * S * HID + (long)B * S * S;
    float* attn;
    if ((long)out_size >= need_with_attn) {
        attn = out + (long)B * S * HID;
    } else {
        void* p = nullptr;
        cudaGetSymbolAddress(&p, g_attn_scratch);
        attn = (float*)p;
    }

    dim3 gA(B, (S + TI_A - 1) / TI_A);
    qk_softmax_kernel<<<gA, 256>>>(q, k, attn, S);

    dim3 gB(B, (S + TI_B - 1) / TI_B);
    out_kernel<<<gB, 256>>>(attn, v, aw, Kp, out, S);
}

// round 8
// speedup vs baseline: 1.2432x; 1.1906x over previous
#include <cuda_runtime.h>
#include <math.h>
#include <stdint.h>

#define HID 512
#define TI_A 32
#define KV   10   // class size (N=K=10 problem family; S = N*K+1)

typedef unsigned long long ull;

__device__ __forceinline__ ull fma2(ull a, ull b, ull c) {
    ull d;
    asm("fma.rn.f32x2 %0, %1, %2, %3;" : "=l"(d) : "l"(a), "l"(b), "l"(c));
    return d;
}
__device__ __forceinline__ ull pack2(float lo, float hi) {
    ull d;
    asm("mov.b64 %0, {%1, %2};" : "=l"(d) : "f"(lo), "f"(hi));
    return d;
}
__device__ __forceinline__ float2 unpack2(ull a) {
    float lo, hi;
    asm("mov.b64 {%0, %1}, %2;" : "=f"(lo), "=f"(hi) : "l"(a));
    return make_float2(lo, hi);
}

// Fallback scratch for attn if d_out doesn't include the attn tensor.
__device__ float g_attn_scratch[64 * 128 * 128];

// ---------------------------------------------------------------------------
// Kernel A: scores = Q K^T / sqrt(H), row softmax, write attn[b][i][j].
// Block: (batch b, 32-row i tile). 256 threads = (ty 0..7) x (tx 0..31).
// Thread micro-tile: 4 i x 4 j, j = {2tx, 2tx+1, 2tx+64, 2tx+65}.
// h processed in 16 chunks of 32 floats with DOUBLE-BUFFERED smem tiles.
// ---------------------------------------------------------------------------
__global__ __launch_bounds__(256) void qk_softmax_kernel(
    const float* __restrict__ q, const float* __restrict__ k,
    float* __restrict__ attn, int S)
{
    __shared__ ull Qs2[2][16][34];    // [buf][h2][i]
    __shared__ ull Ks2[2][16][130];   // [buf][h2][j]

    const int b   = blockIdx.x;
    const int i0  = blockIdx.y * TI_A;
    const int tid = threadIdx.x;
    const int tx  = tid & 31;
    const int ty  = tid >> 5;
    const int iy4 = ty * 4;
    const int h2l  = tx & 15;               // h-pair lane for loads (0..15)
    const int rsel = ty * 2 + (tx >> 4);    // row selector for loads (0..15)

    const float* qb = q + (size_t)b * S * HID;
    const float* kb = k + (size_t)b * S * HID;

    ull acc2[4][4];
#pragma unroll
    for (int a = 0; a < 4; ++a)
#pragma unroll
        for (int c = 0; c < 4; ++c) acc2[a][c] = 0ull;

    auto load_chunk = [&](int c, int buf) {
        int h0 = c * 32;
#pragma unroll
        for (int r = 0; r < 2; ++r) {
            int il = rsel + 16 * r;
            int i  = i0 + il;
            float2 val = (i < S) ? *(const float2*)(qb + (size_t)i * HID + h0 + h2l * 2)
                                 : make_float2(0.f, 0.f);
            *(float2*)&Qs2[buf][h2l][il] = val;
        }
#pragma unroll
        for (int r = 0; r < 8; ++r) {
            int j = rsel + 16 * r;
            float2 val = (j < S) ? *(const float2*)(kb + (size_t)j * HID + h0 + h2l * 2)
                                 : make_float2(0.f, 0.f);
            *(float2*)&Ks2[buf][h2l][j] = val;
        }
    };

    load_chunk(0, 0);
    __syncthreads();

#pragma unroll 1
    for (int c = 0; c < 16; ++c) {
        int cur = c & 1;
        if (c + 1 < 16) load_chunk(c + 1, cur ^ 1);   // overlap with compute

#pragma unroll
        for (int h2 = 0; h2 < 16; ++h2) {
            ulonglong2 qa = *(const ulonglong2*)&Qs2[cur][h2][iy4];
            ulonglong2 qc = *(const ulonglong2*)&Qs2[cur][h2][iy4 + 2];
            ulonglong2 ka = *(const ulonglong2*)&Ks2[cur][h2][2 * tx];
            ulonglong2 kc = *(const ulonglong2*)&Ks2[cur][h2][2 * tx + 64];
            acc2[0][0] = fma2(qa.x, ka.x, acc2[0][0]);
            acc2[0][1] = fma2(qa.x, ka.y, acc2[0][1]);
            acc2[0][2] = fma2(qa.x, kc.x, acc2[0][2]);
            acc2[0][3] = fma2(qa.x, kc.y, acc2[0][3]);
            acc2[1][0] = fma2(qa.y, ka.x, acc2[1][0]);
            acc2[1][1] = fma2(qa.y, ka.y, acc2[1][1]);
            acc2[1][2] = fma2(qa.y, kc.x, acc2[1][2]);
            acc2[1][3] = fma2(qa.y, kc.y, acc2[1][3]);
            acc2[2][0] = fma2(qc.x, ka.x, acc2[2][0]);
            acc2[2][1] = fma2(qc.x, ka.y, acc2[2][1]);
            acc2[2][2] = fma2(qc.x, kc.x, acc2[2][2]);
            acc2[2][3] = fma2(qc.x, kc.y, acc2[2][3]);
            acc2[3][0] = fma2(qc.y, ka.x, acc2[3][0]);
            acc2[3][1] = fma2(qc.y, ka.y, acc2[3][1]);
            acc2[3][2] = fma2(qc.y, kc.x, acc2[3][2]);
            acc2[3][3] = fma2(qc.y, kc.y, acc2[3][3]);
        }
        __syncthreads();
    }

    const float inv_t = 0.04419417382415922f;  // 1/sqrt(512)

    const int c0 = 2 * tx;
    const int c2 = 2 * tx + 64;
    const bool v0 = (c0    ) < S;
    const bool v1 = (c0 + 1) < S;
    const bool v2 = (c2    ) < S;
    const bool v3 = (c2 + 1) < S;

#pragma unroll
    for (int si = 0; si < 4; ++si) {
        int i = i0 + iy4 + si;
        float2 a0 = unpack2(acc2[si][0]);
        float2 a1 = unpack2(acc2[si][1]);
        float2 a2 = unpack2(acc2[si][2]);
        float2 a3 = unpack2(acc2[si][3]);
        float s0 = v0 ? (a0.x + a0.y) * inv_t : -INFINITY;
        float s1 = v1 ? (a1.x + a1.y) * inv_t : -INFINITY;
        float s2 = v2 ? (a2.x + a2.y) * inv_t : -INFINITY;
        float s3 = v3 ? (a3.x + a3.y) * inv_t : -INFINITY;

        float m = fmaxf(fmaxf(s0, s1), fmaxf(s2, s3));
#pragma unroll
        for (int o = 16; o > 0; o >>= 1)
            m = fmaxf(m, __shfl_xor_sync(0xffffffffu, m, o));

        float e0 = __expf(s0 - m);
        float e1 = __expf(s1 - m);
        float e2 = __expf(s2 - m);
        float e3 = __expf(s3 - m);

        float sum = e0 + e1 + e2 + e3;
#pragma unroll
        for (int o = 16; o > 0; o >>= 1)
            sum += __shfl_xor_sync(0xffffffffu, sum, o);

        float rinv = 1.0f / sum;
        if (i < S) {
            float* row = attn + ((size_t)b * S + i) * S;
            if (v0) row[c0]     = e0 * rinv;
            if (v1) row[c0 + 1] = e1 * rinv;
            if (v2) row[c2]     = e2 * rinv;
            if (v3) row[c2 + 1] = e3 * rinv;
        }
    }
}

// ---------------------------------------------------------------------------
// Kernel B v2: CLASS-ALIGNED tiles. Grid (B, ceil(S/KV)).
// Tile by covers rows [by*KV, min(by*KV+KV, S)). For by < (S-1)/KV this is
// exactly one class (10 rows); the last tile is the query row alone.
//   class rows: out = w2*F + (w1-w2)*C + (w0-w1)*a_ii*v_i + (w3-w2)*a_iq*v_q
//   query row:  out = w4*F + (w5-w4)*a_qq*v_q
// All rows in a class tile share the class j-range == the tile's own rows,
// so C is computed with the same row-pair fma2 body as F (10 prefetched
// LDG + 100 fma2 per thread instead of 160 serial LDG + 320 FFMA).
// 256 threads; thread t owns h = {2t, 2t+1} for all tile rows.
// ---------------------------------------------------------------------------
__global__ __launch_bounds__(256, 3) void out_kernel(
    const float* __restrict__ attn, const float* __restrict__ v,
    const float* __restrict__ aw,
    float* __restrict__ out, int S)
{
    __shared__ float AsT[102][12];   // [j][ii], 48B rows (16B aligned)

    const int b   = blockIdx.x;
    const int i0  = blockIdx.y * KV;
    const int t   = threadIdx.x;     // 0..255
    const int h   = 2 * t;
    const int NKq = S - 1;
    const int nrows = (S - i0 < KV) ? (S - i0) : KV;

    const float* vb = v + (size_t)b * S * HID;

    // Stage attn tile transposed: AsT[j][ii] = attn[i0+ii][j]
    for (int idx = t; idx < 102 * 12; idx += 256) {
        int jj = idx / 12;
        int ii = idx - jj * 12;
        float a = 0.f;
        if (ii < nrows && jj < S)
            a = attn[((size_t)b * S + i0 + ii) * S + jj];
        AsT[jj][ii] = a;
    }
    __syncthreads();

    // F0[r] = (F[2r][h], F[2r+1][h]);  F1[r] same at h+1.  5 row-pairs.
    ull F0[5], F1[5];
#pragma unroll
    for (int r = 0; r < 5; ++r) { F0[r] = 0ull; F1[r] = 0ull; }

    const float2 fz = make_float2(0.f, 0.f);

    auto body = [&](ull* A0, ull* A1, int j, float2 vc) {
        ull vlo = pack2(vc.x, vc.x);
        ull vhi = pack2(vc.y, vc.y);
        ulonglong2 a01 = *(const ulonglong2*)&AsT[j][0];
        ulonglong2 a23 = *(const ulonglong2*)&AsT[j][4];
        ull        a4  = *(const ull*)&AsT[j][8];
        A0[0] = fma2(vlo, a01.x, A0[0]);  A1[0] = fma2(vhi, a01.x, A1[0]);
        A0[1] = fma2(vlo, a01.y, A0[1]);  A1[1] = fma2(vhi, a01.y, A1[1]);
        A0[2] = fma2(vlo, a23.x, A0[2]);  A1[2] = fma2(vhi, a23.x, A1[2]);
        A0[3] = fma2(vlo, a23.y, A0[3]);  A1[3] = fma2(vhi, a23.y, A1[3]);
        A0[4] = fma2(vlo, a4,    A0[4]);  A1[4] = fma2(vhi, a4,    A1[4]);
    };

    // Main F loop over all j, 4-deep register prefetch ring
    float2 p0 = (0 < S) ? *(const float2*)(vb + 0 * (size_t)HID + h) : fz;
    float2 p1 = (1 < S) ? *(const float2*)(vb + 1 * (size_t)HID + h) : fz;
    float2 p2 = (2 < S) ? *(const float2*)(vb + 2 * (size_t)HID + h) : fz;
    float2 p3 = (3 < S) ? *(const float2*)(vb + 3 * (size_t)HID + h) : fz;

    int j = 0;
#pragma unroll 1
    for (; j + 3 < S; j += 4) {
        float2 n0 = (j + 4 < S) ? *(const float2*)(vb + (size_t)(j + 4) * HID + h) : fz;
        float2 n1 = (j + 5 < S) ? *(const float2*)(vb + (size_t)(j + 5) * HID + h) : fz;
        float2 n2 = (j + 6 < S) ? *(const float2*)(vb + (size_t)(j + 6) * HID + h) : fz;
        float2 n3 = (j + 7 < S) ? *(const float2*)(vb + (size_t)(j + 7) * HID + h) : fz;
        body(F0, F1, j + 0, p0);
        body(F0, F1, j + 1, p1);
        body(F0, F1, j + 2, p2);
        body(F0, F1, j + 3, p3);
        p0 = n0; p1 = n1; p2 = n2; p3 = n3;
    }
    if (j < S)     body(F0, F1, j,     p0);
    if (j + 1 < S) body(F0, F1, j + 1, p1);
    if (j + 2 < S) body(F0, F1, j + 2, p2);

    const float2 vq = *(const float2*)(vb + (size_t)NKq * HID + h);

    if (i0 >= NKq) {
        // ---- query tile: single row NKq at local ii = 0 ----
        const float2 w4 = *(const float2*)(aw + 4 * HID + h);
        const float2 w5 = *(const float2*)(aw + 5 * HID + h);
        float Fx = unpack2(F0[0]).x;
        float Fy = unpack2(F1[0]).x;
        float aqq = AsT[NKq][0];
        float2 o;
        o.x = w4.x * Fx + (w5.x - w4.x) * aqq * vq.x;
        o.y = w4.y * Fy + (w5.y - w4.y) * aqq * vq.y;
        *(float2*)(out + ((size_t)b * S + NKq) * HID + h) = o;
        return;
    }

    // ---- class tile: C over the tile's own j-range [i0, i0+KV) ----
    ull C0[5], C1[5];
#pragma unroll
    for (int r = 0; r < 5; ++r) { C0[r] = 0ull; C1[r] = 0ull; }

    // two half-batches of 5 prefetched loads each
    {
        float2 u0 = *(const float2*)(vb + (size_t)(i0 + 0) * HID + h);
        float2 u1 = *(const float2*)(vb + (size_t)(i0 + 1) * HID + h);
        float2 u2 = *(const float2*)(vb + (size_t)(i0 + 2) * HID + h);
        float2 u3 = *(const float2*)(vb + (size_t)(i0 + 3) * HID + h);
        float2 u4 = *(const float2*)(vb + (size_t)(i0 + 4) * HID + h);
        body(C0, C1, i0 + 0, u0);
        body(C0, C1, i0 + 1, u1);
        body(C0, C1, i0 + 2, u2);
        body(C0, C1, i0 + 3, u3);
        body(C0, C1, i0 + 4, u4);
        u0 = *(const float2*)(vb + (size_t)(i0 + 5) * HID + h);
        u1 = *(const float2*)(vb + (size_t)(i0 + 6) * HID + h);
        u2 = *(const float2*)(vb + (size_t)(i0 + 7) * HID + h);
        u3 = *(const float2*)(vb + (size_t)(i0 + 8) * HID + h);
        u4 = *(const float2*)(vb + (size_t)(i0 + 9) * HID + h);
        body(C0, C1, i0 + 5, u0);
        body(C0, C1, i0 + 6, u1);
        body(C0, C1, i0 + 7, u2);
        body(C0, C1, i0 + 8, u3);
        body(C0, C1, i0 + 9, u4);
    }

    // Weight vectors at this 2-wide h slice
    const float2 w0 = *(const float2*)(aw + 0 * HID + h);
    const float2 w1 = *(const float2*)(aw + 1 * HID + h);
    const float2 w2 = *(const float2*)(aw + 2 * HID + h);
    const float2 w3 = *(const float2*)(aw + 3 * HID + h);

    const float2 d12 = make_float2(w1.x - w2.x, w1.y - w2.y);
    const float2 d01 = make_float2(w0.x - w1.x, w0.y - w1.y);
    const float2 d32 = make_float2(w3.x - w2.x, w3.y - w2.y);

#pragma unroll
    for (int r = 0; r < 5; ++r) {
        float2 f0 = unpack2(F0[r]);   // F[2r][h], F[2r+1][h]
        float2 f1 = unpack2(F1[r]);   // F[2r][h+1], F[2r+1][h+1]
        float2 c0 = unpack2(C0[r]);
        float2 c1 = unpack2(C1[r]);

#pragma unroll
        for (int s = 0; s < 2; ++s) {
            int k = 2 * r + s;
            int i = i0 + k;
            float Fx = s ? f0.y : f0.x;
            float Fy = s ? f1.y : f1.x;
            float Cx = s ? c0.y : c0.x;
            float Cy = s ? c1.y : c1.x;
            float aii = AsT[i][k];
            float aiq = AsT[NKq][k];
            float2 vi = *(const float2*)(vb + (size_t)i * HID + h);  // L1-hot
            float2 o;
            o.x = w2.x * Fx + d12.x * Cx + d01.x * aii * vi.x + d32.x * aiq * vq.x;
            o.y = w2.y * Fy + d12.y * Cy + d01.y * aii * vi.y + d32.y * aiq * vq.y;
            *(float2*)(out + ((size_t)b * S + i) * HID + h) = o;
        }
    }
}

// ---------------------------------------------------------------------------
extern "C" void kernel_launch(void* const* d_in, const int* in_sizes, int n_in,
                              void* d_out, int out_size)
{
    const float* q  = (const float*)d_in[0];
    const float* k  = (const float*)d_in[1];
    const float* v  = (const float*)d_in[2];
    const float* aw = (const float*)d_in[3];

    long rows = (long)in_sizes[0] / HID;   // B * S
    int B = 64;
    int S = (int)(rows / B);
    if (S <= 0 || (long)B * S != rows) { B = 1; S = (int)rows; }

    float* out = (float*)d_out;
    long need_with_attn = (long)B * S * HID + (long)B * S * S;
    float* attn;
    if ((long)out_size >= need_with_attn) {
        attn = out + (long)B * S * HID;
    } else {
        void* p = nullptr;
        cudaGetSymbolAddress(&p, g_attn_scratch);
        attn = (float*)p;
    }

    dim3 gA(B, (S + TI_A - 1) / TI_A);
    qk_softmax_kernel<<<gA, 256>>>(q, k, attn, S);

    dim3 gB(B, (S + KV - 1) / KV);
    out_kernel<<<gB, 256>>>(attn, v, aw, out, S);
}